// round 1
// baseline (speedup 1.0000x reference)
#include <cuda_runtime.h>
#include <math.h>

#define BB 8
#define TT 2048
#define DD 1024
#define HH 128
#define MM (BB*TT)

// scratch: q, k (post-RoPE) and v projections, fp32
__device__ float g_q[MM*HH];
__device__ float g_k[MM*HH];
__device__ float g_v[MM*HH];

// ---------------------------------------------------------------------------
// Kernel 1: fused QKV projection + RoPE epilogue (q, k only)
// grid = (256, 3): blockIdx.x -> 64-row M tile, blockIdx.y -> {q,k,v}
// block = 256 threads; per-thread 4x8 micro-tile of the 64x128 CTA tile
// ---------------------------------------------------------------------------
__global__ __launch_bounds__(256) void qkv_rope_kernel(
    const float* __restrict__ x,
    const float* __restrict__ Wq,
    const float* __restrict__ Wk,
    const float* __restrict__ Wv)
{
    __shared__ float xs[64][33];    // pad 33 -> conflict-free scalar reads
    __shared__ float ws[32][128];

    const int tid = threadIdx.x;
    const int mat = blockIdx.y;
    const float* __restrict__ W = (mat == 0) ? Wq : ((mat == 1) ? Wk : Wv);
    float* __restrict__ outp     = (mat == 0) ? g_q : ((mat == 1) ? g_k : g_v);

    const int m0 = blockIdx.x * 64;
    const int rt = tid >> 4;          // 0..15 -> rows rt*4 .. rt*4+3
    const int ct = tid & 15;          // 0..15 -> cols ct*8 .. ct*8+7
    const int r4 = rt * 4;
    const int c8 = ct * 8;

    // loader mapping
    const int lrow = tid >> 2;        // 0..63
    const int lcg  = (tid & 3) * 8;   // 0,8,16,24
    const int wrow = tid >> 3;        // 0..31
    const int wcol = (tid & 7) * 16;  // 0..112

    float acc[4][8];
#pragma unroll
    for (int i = 0; i < 4; i++)
#pragma unroll
        for (int j = 0; j < 8; j++) acc[i][j] = 0.0f;

    for (int k0 = 0; k0 < DD; k0 += 32) {
        // load x tile 64x32
        const float* xp = x + (size_t)(m0 + lrow) * DD + k0 + lcg;
        float4 a0 = *(const float4*)xp;
        float4 a1 = *(const float4*)(xp + 4);
        xs[lrow][lcg + 0] = a0.x; xs[lrow][lcg + 1] = a0.y;
        xs[lrow][lcg + 2] = a0.z; xs[lrow][lcg + 3] = a0.w;
        xs[lrow][lcg + 4] = a1.x; xs[lrow][lcg + 5] = a1.y;
        xs[lrow][lcg + 6] = a1.z; xs[lrow][lcg + 7] = a1.w;

        // load W tile 32x128
        const float* wp = W + (size_t)(k0 + wrow) * HH + wcol;
        float4 b0 = *(const float4*)(wp + 0);
        float4 b1 = *(const float4*)(wp + 4);
        float4 b2 = *(const float4*)(wp + 8);
        float4 b3 = *(const float4*)(wp + 12);
        *(float4*)&ws[wrow][wcol + 0]  = b0;
        *(float4*)&ws[wrow][wcol + 4]  = b1;
        *(float4*)&ws[wrow][wcol + 8]  = b2;
        *(float4*)&ws[wrow][wcol + 12] = b3;

        __syncthreads();

#pragma unroll 8
        for (int kk = 0; kk < 32; kk++) {
            float av0 = xs[r4 + 0][kk];
            float av1 = xs[r4 + 1][kk];
            float av2 = xs[r4 + 2][kk];
            float av3 = xs[r4 + 3][kk];
            float4 bv0 = *(const float4*)&ws[kk][c8];
            float4 bv1 = *(const float4*)&ws[kk][c8 + 4];
            float bv[8] = {bv0.x, bv0.y, bv0.z, bv0.w, bv1.x, bv1.y, bv1.z, bv1.w};
#pragma unroll
            for (int j = 0; j < 8; j++) {
                acc[0][j] += av0 * bv[j];
                acc[1][j] += av1 * bv[j];
                acc[2][j] += av2 * bv[j];
                acc[3][j] += av3 * bv[j];
            }
        }
        __syncthreads();
    }

    // RoPE epilogue for q (mat 0) and k (mat 1)
    if (mat < 2) {
#pragma unroll
        for (int i = 0; i < 4; i++) {
            int m = m0 + r4 + i;
            float tpos = (float)(m & (TT - 1));
#pragma unroll
            for (int p = 0; p < 4; p++) {
                int col = c8 + p * 2;
                float freq = powf(10000.0f, -(float)(col >> 1) / 64.0f);
                float ang = tpos * freq;
                float sn, cs;
                sincosf(ang, &sn, &cs);
                float x0 = acc[i][p * 2 + 0];
                float x1 = acc[i][p * 2 + 1];
                acc[i][p * 2 + 0] = x0 * cs - x1 * sn;
                acc[i][p * 2 + 1] = x0 * sn + x1 * cs;
            }
        }
    }

#pragma unroll
    for (int i = 0; i < 4; i++) {
        float* op = outp + (size_t)(m0 + r4 + i) * HH + c8;
        float4 s0 = make_float4(acc[i][0], acc[i][1], acc[i][2], acc[i][3]);
        float4 s1 = make_float4(acc[i][4], acc[i][5], acc[i][6], acc[i][7]);
        *(float4*)(op + 0) = s0;
        *(float4*)(op + 4) = s1;
    }
}

// ---------------------------------------------------------------------------
// Kernel 2: causal flash attention, fp32
// grid = (32, 8): blockIdx.x -> 64-row q tile (reversed for load balance),
//                 blockIdx.y -> batch.  block = 256 threads.
// smem (floats): Qs 64*128 | Ks 64*129 | Vs 64*128 | Ps 64*65  = 28800 floats
// ---------------------------------------------------------------------------
#define QS_OFF 0
#define KS_OFF 8192
#define VS_OFF (8192 + 64*129)
#define PS_OFF (VS_OFF + 8192)
#define SMEM_FLOATS (PS_OFF + 64*65)

__global__ __launch_bounds__(256) void attn_kernel(float* __restrict__ out)
{
    extern __shared__ float smem[];
    float* Qs = smem + QS_OFF;   // stride 128 (scaled by 1/sqrt(H))
    float* Ks = smem + KS_OFF;   // stride 129 (conflict-free column reads)
    float* Vs = smem + VS_OFF;   // stride 128
    float* Ps = smem + PS_OFF;   // stride 65

    const int tid = threadIdx.x;
    const int b = blockIdx.y;
    const int i0 = (gridDim.x - 1 - blockIdx.x) * 64;  // heavy tiles first

    const int rt = tid >> 4;         // row group: rows rt*4..rt*4+3
    const int ct = tid & 15;
    const int r4 = rt * 4;
    const int c4 = ct * 4;           // S-phase cols
    const int c8 = ct * 8;           // O-phase cols

    const float qscale = 0.08838834764831845f;  // 1/sqrt(128)

    // load Q tile (scaled)
    {
        const float4* src = (const float4*)(g_q + (size_t)(b * TT + i0) * HH);
        float4* dst = (float4*)Qs;
        for (int i = tid; i < 2048; i += 256) {
            float4 v = src[i];
            v.x *= qscale; v.y *= qscale; v.z *= qscale; v.w *= qscale;
            dst[i] = v;
        }
    }

    float o[4][8];
    float mrow[4], lrow[4];
#pragma unroll
    for (int i = 0; i < 4; i++) {
        mrow[i] = -1e30f; lrow[i] = 0.0f;
#pragma unroll
        for (int j = 0; j < 8; j++) o[i][j] = 0.0f;
    }

    const int ntiles = i0 / 64 + 1;
    for (int jt = 0; jt < ntiles; jt++) {
        const int j0 = jt * 64;
        __syncthreads();  // protect smem reuse from previous iteration

        // load K (stride 129, scalar stores) and V (stride 128, float4)
        {
            const float* kbase = g_k + (size_t)(b * TT + j0) * HH;
            for (int seg = tid; seg < 2048; seg += 256) {
                int row = seg >> 5;
                int col = (seg & 31) * 4;
                float4 v = *(const float4*)(kbase + row * HH + col);
                float* d = Ks + row * 129 + col;
                d[0] = v.x; d[1] = v.y; d[2] = v.z; d[3] = v.w;
            }
            const float4* vbase = (const float4*)(g_v + (size_t)(b * TT + j0) * HH);
            float4* vdst = (float4*)Vs;
            for (int i = tid; i < 2048; i += 256) vdst[i] = vbase[i];
        }
        __syncthreads();

        // S = Q K^T  (each thread: 4 rows x 4 cols)
        float s[4][4];
#pragma unroll
        for (int i = 0; i < 4; i++)
#pragma unroll
            for (int j = 0; j < 4; j++) s[i][j] = 0.0f;

        const float* q0 = Qs + (r4 + 0) * 128;
        const float* q1 = Qs + (r4 + 1) * 128;
        const float* q2 = Qs + (r4 + 2) * 128;
        const float* q3 = Qs + (r4 + 3) * 128;
        const float* k0 = Ks + (c4 + 0) * 129;
        const float* k1 = Ks + (c4 + 1) * 129;
        const float* k2 = Ks + (c4 + 2) * 129;
        const float* k3 = Ks + (c4 + 3) * 129;

#pragma unroll 8
        for (int d = 0; d < 128; d++) {
            float qa0 = q0[d], qa1 = q1[d], qa2 = q2[d], qa3 = q3[d];
            float kb0 = k0[d], kb1 = k1[d], kb2 = k2[d], kb3 = k3[d];
            s[0][0] += qa0 * kb0; s[0][1] += qa0 * kb1; s[0][2] += qa0 * kb2; s[0][3] += qa0 * kb3;
            s[1][0] += qa1 * kb0; s[1][1] += qa1 * kb1; s[1][2] += qa1 * kb2; s[1][3] += qa1 * kb3;
            s[2][0] += qa2 * kb0; s[2][1] += qa2 * kb1; s[2][2] += qa2 * kb2; s[2][3] += qa2 * kb3;
            s[3][0] += qa3 * kb0; s[3][1] += qa3 * kb1; s[3][2] += qa3 * kb2; s[3][3] += qa3 * kb3;
        }

        // causal mask on the diagonal tile
        if (j0 == i0) {
#pragma unroll
            for (int i = 0; i < 4; i++)
#pragma unroll
                for (int j = 0; j < 4; j++)
                    if (c4 + j > r4 + i) s[i][j] = -1e30f;
        }

        // online softmax (row groups of 16 lanes share a warp half)
        float scl[4];
#pragma unroll
        for (int i = 0; i < 4; i++) {
            float mt = fmaxf(fmaxf(s[i][0], s[i][1]), fmaxf(s[i][2], s[i][3]));
            mt = fmaxf(mt, __shfl_xor_sync(0xffffffffu, mt, 8));
            mt = fmaxf(mt, __shfl_xor_sync(0xffffffffu, mt, 4));
            mt = fmaxf(mt, __shfl_xor_sync(0xffffffffu, mt, 2));
            mt = fmaxf(mt, __shfl_xor_sync(0xffffffffu, mt, 1));
            float mnew = fmaxf(mrow[i], mt);
            float p0 = __expf(s[i][0] - mnew);
            float p1 = __expf(s[i][1] - mnew);
            float p2 = __expf(s[i][2] - mnew);
            float p3 = __expf(s[i][3] - mnew);
            float rs = p0 + p1 + p2 + p3;
            rs += __shfl_xor_sync(0xffffffffu, rs, 8);
            rs += __shfl_xor_sync(0xffffffffu, rs, 4);
            rs += __shfl_xor_sync(0xffffffffu, rs, 2);
            rs += __shfl_xor_sync(0xffffffffu, rs, 1);
            float sc = __expf(mrow[i] - mnew);
            lrow[i] = lrow[i] * sc + rs;
            mrow[i] = mnew;
            scl[i] = sc;
            float* prow = Ps + (r4 + i) * 65 + c4;
            prow[0] = p0; prow[1] = p1; prow[2] = p2; prow[3] = p3;
        }
        __syncthreads();  // Ps ready (K reads done above)

        // O = O*scale + P V
#pragma unroll
        for (int i = 0; i < 4; i++)
#pragma unroll
            for (int j = 0; j < 8; j++) o[i][j] *= scl[i];

        const float* p0r = Ps + (r4 + 0) * 65;
        const float* p1r = Ps + (r4 + 1) * 65;
        const float* p2r = Ps + (r4 + 2) * 65;
        const float* p3r = Ps + (r4 + 3) * 65;

#pragma unroll 4
        for (int c = 0; c < 64; c++) {
            float pa0 = p0r[c], pa1 = p1r[c], pa2 = p2r[c], pa3 = p3r[c];
            float4 va = *(const float4*)&Vs[c * 128 + c8];
            float4 vb = *(const float4*)&Vs[c * 128 + c8 + 4];
            float vv[8] = {va.x, va.y, va.z, va.w, vb.x, vb.y, vb.z, vb.w};
#pragma unroll
            for (int j = 0; j < 8; j++) {
                o[0][j] += pa0 * vv[j];
                o[1][j] += pa1 * vv[j];
                o[2][j] += pa2 * vv[j];
                o[3][j] += pa3 * vv[j];
            }
        }
    }

    // normalize and store
#pragma unroll
    for (int i = 0; i < 4; i++) {
        float inv = 1.0f / lrow[i];
        float* op = out + (size_t)(b * TT + i0 + r4 + i) * HH + c8;
        float4 s0 = make_float4(o[i][0] * inv, o[i][1] * inv, o[i][2] * inv, o[i][3] * inv);
        float4 s1 = make_float4(o[i][4] * inv, o[i][5] * inv, o[i][6] * inv, o[i][7] * inv);
        *(float4*)(op + 0) = s0;
        *(float4*)(op + 4) = s1;
    }
}

// ---------------------------------------------------------------------------
extern "C" void kernel_launch(void* const* d_in, const int* in_sizes, int n_in,
                              void* d_out, int out_size)
{
    const float* x  = (const float*)d_in[0];
    const float* Wq = (const float*)d_in[1];
    const float* Wk = (const float*)d_in[2];
    const float* Wv = (const float*)d_in[3];
    float* out = (float*)d_out;

    qkv_rope_kernel<<<dim3(MM / 64, 3), 256>>>(x, Wq, Wk, Wv);

    static int smem_set = 0;
    size_t smem_bytes = SMEM_FLOATS * sizeof(float);  // 115200 B
    if (!smem_set) {
        cudaFuncSetAttribute(attn_kernel,
                             cudaFuncAttributeMaxDynamicSharedMemorySize,
                             (int)smem_bytes);
        smem_set = 1;
    }
    attn_kernel<<<dim3(TT / 64, BB), 256, smem_bytes>>>(out);
}

// round 6
// speedup vs baseline: 3.1276x; 3.1276x over previous
#include <cuda_runtime.h>
#include <cuda_bf16.h>
#include <math.h>
#include <stdint.h>

#define BB 8
#define TT 2048
#define DD 1024
#define HH 128
#define MM (BB*TT)

// ---------------- device-global scratch (allocation-guard safe) ------------
__device__ __nv_bfloat16 g_xhi[MM*DD];
__device__ __nv_bfloat16 g_xlo[MM*DD];
__device__ __nv_bfloat16 g_wthi[3*HH*DD];   // W^T [mat][n][k]
__device__ __nv_bfloat16 g_wtlo[3*HH*DD];
__device__ __nv_bfloat16 g_qhi[MM*HH];      // post-RoPE, pre-scaled by 1/sqrt(H)
__device__ __nv_bfloat16 g_qlo[MM*HH];
__device__ __nv_bfloat16 g_khi[MM*HH];      // post-RoPE
__device__ __nv_bfloat16 g_klo[MM*HH];
__device__ __nv_bfloat16 g_vhi[MM*HH];
__device__ __nv_bfloat16 g_vlo[MM*HH];

// ---------------- PTX helpers (base sm_103-safe: no tcgen05!) --------------
__device__ __forceinline__ uint32_t smem_u32(const void* p) {
    uint32_t a;
    asm("{ .reg .u64 t; cvta.to.shared.u64 t, %1; cvt.u32.u64 %0, t; }"
        : "=r"(a) : "l"(p));
    return a;
}

__device__ __forceinline__ void ldsm_x4(uint32_t& a0, uint32_t& a1,
                                        uint32_t& a2, uint32_t& a3, uint32_t addr) {
    asm volatile("ldmatrix.sync.aligned.m8n8.x4.shared.b16 {%0,%1,%2,%3}, [%4];"
                 : "=r"(a0), "=r"(a1), "=r"(a2), "=r"(a3) : "r"(addr));
}
__device__ __forceinline__ void ldsm_x2(uint32_t& b0, uint32_t& b1, uint32_t addr) {
    asm volatile("ldmatrix.sync.aligned.m8n8.x2.shared.b16 {%0,%1}, [%2];"
                 : "=r"(b0), "=r"(b1) : "r"(addr));
}
__device__ __forceinline__ void ldsm_x2t(uint32_t& b0, uint32_t& b1, uint32_t addr) {
    asm volatile("ldmatrix.sync.aligned.m8n8.x2.trans.shared.b16 {%0,%1}, [%2];"
                 : "=r"(b0), "=r"(b1) : "r"(addr));
}

__device__ __forceinline__ void mma16816(float* c, const uint32_t* a,
                                         uint32_t b0, uint32_t b1) {
    asm volatile(
        "mma.sync.aligned.m16n8k16.row.col.f32.bf16.bf16.f32 "
        "{%0,%1,%2,%3}, {%4,%5,%6,%7}, {%8,%9}, {%0,%1,%2,%3};"
        : "+f"(c[0]), "+f"(c[1]), "+f"(c[2]), "+f"(c[3])
        : "r"(a[0]), "r"(a[1]), "r"(a[2]), "r"(a[3]), "r"(b0), "r"(b1));
}

__device__ __forceinline__ uint32_t pack_bf16x2(float a, float b) {
    __nv_bfloat162 h(__float2bfloat16(a), __float2bfloat16(b));  // low=a, high=b
    return *reinterpret_cast<uint32_t*>(&h);
}

// ---------------------------------------------------------------------------
// fp32 -> split bf16 conversions
// ---------------------------------------------------------------------------
__global__ __launch_bounds__(256) void convert_x_kernel(const float* __restrict__ x)
{
    int i = blockIdx.x * 256 + threadIdx.x;          // over MM*DD/4
    float4 v = ((const float4*)x)[i];
    __nv_bfloat16 h0 = __float2bfloat16(v.x);
    __nv_bfloat16 h1 = __float2bfloat16(v.y);
    __nv_bfloat16 h2 = __float2bfloat16(v.z);
    __nv_bfloat16 h3 = __float2bfloat16(v.w);
    float l0 = v.x - __bfloat162float(h0);
    float l1 = v.y - __bfloat162float(h1);
    float l2 = v.z - __bfloat162float(h2);
    float l3 = v.w - __bfloat162float(h3);
    __nv_bfloat162* ph = (__nv_bfloat162*)g_xhi;
    __nv_bfloat162* pl = (__nv_bfloat162*)g_xlo;
    ph[2*i]   = __nv_bfloat162(h0, h1);
    ph[2*i+1] = __nv_bfloat162(h2, h3);
    pl[2*i]   = __nv_bfloat162(__float2bfloat16(l0), __float2bfloat16(l1));
    pl[2*i+1] = __nv_bfloat162(__float2bfloat16(l2), __float2bfloat16(l3));
}

__global__ __launch_bounds__(256) void convert_w_kernel(
    const float* __restrict__ Wq, const float* __restrict__ Wk,
    const float* __restrict__ Wv)
{
    int mat = blockIdx.y;
    const float* __restrict__ W = (mat == 0) ? Wq : ((mat == 1) ? Wk : Wv);
    int i = blockIdx.x * 256 + threadIdx.x;          // 0 .. DD*HH-1
    int k = i >> 7;
    int n = i & 127;
    float w = W[i];
    __nv_bfloat16 h = __float2bfloat16(w);
    float lo = w - __bfloat162float(h);
    size_t o = (size_t)mat * HH * DD + (size_t)n * DD + k;
    g_wthi[o] = h;
    g_wtlo[o] = __float2bfloat16(lo);
}

// ---------------------------------------------------------------------------
// QKV projection via mma.sync split-bf16 + RoPE epilogue, split-bf16 outputs
// grid=(128,3), 256 threads (8 warps x 16 rows). C tile 128m x 128n.
// smem per 64-k chunk: Xhi/Xlo [128][72], WThi/WTlo [128][72]  (73728 B)
// ---------------------------------------------------------------------------
#define QP 72

__global__ __launch_bounds__(256) void qkv_mma_kernel()
{
    extern __shared__ __nv_bfloat16 smq[];
    __nv_bfloat16* sxh = smq;
    __nv_bfloat16* sxl = smq + 128*QP;
    __nv_bfloat16* swh = smq + 2*128*QP;
    __nv_bfloat16* swl = smq + 3*128*QP;

    const int tid = threadIdx.x;
    const int w   = tid >> 5;
    const int lane= tid & 31;
    const int mat = blockIdx.y;
    const int m0  = blockIdx.x * 128;

    const __nv_bfloat16* __restrict__ Xh = g_xhi + (size_t)m0 * DD;
    const __nv_bfloat16* __restrict__ Xl = g_xlo + (size_t)m0 * DD;
    const __nv_bfloat16* __restrict__ Bh = g_wthi + (size_t)mat * HH * DD;
    const __nv_bfloat16* __restrict__ Bl = g_wtlo + (size_t)mat * HH * DD;

    float c[16][4];
#pragma unroll
    for (int nt = 0; nt < 16; nt++)
#pragma unroll
        for (int e = 0; e < 4; e++) c[nt][e] = 0.0f;

    for (int kc = 0; kc < 16; kc++) {
        const int kb = kc * 64;
        // stage 4 tiles: 128 rows x 64 halves (128B/row), padded stride 72
#pragma unroll
        for (int it = 0; it < 4; it++) {
            int idx = it * 256 + tid;            // 0..1023
            int row = idx >> 3, seg = idx & 7;
            *(uint4*)(sxh + row*QP + seg*8) = *(const uint4*)(Xh + (size_t)row*DD + kb + seg*8);
        }
#pragma unroll
        for (int it = 0; it < 4; it++) {
            int idx = it * 256 + tid;
            int row = idx >> 3, seg = idx & 7;
            *(uint4*)(sxl + row*QP + seg*8) = *(const uint4*)(Xl + (size_t)row*DD + kb + seg*8);
        }
#pragma unroll
        for (int it = 0; it < 4; it++) {
            int idx = it * 256 + tid;
            int row = idx >> 3, seg = idx & 7;
            *(uint4*)(swh + row*QP + seg*8) = *(const uint4*)(Bh + (size_t)row*DD + kb + seg*8);
        }
#pragma unroll
        for (int it = 0; it < 4; it++) {
            int idx = it * 256 + tid;
            int row = idx >> 3, seg = idx & 7;
            *(uint4*)(swl + row*QP + seg*8) = *(const uint4*)(Bl + (size_t)row*DD + kb + seg*8);
        }
        __syncthreads();

        // A fragments for this chunk (4 k-tiles of 16)
        uint32_t ah[4][4], al[4][4];
        {
            int r = w*16 + (lane & 7) + ((lane >> 3) & 1) * 8;
            int cg = ((lane >> 4) & 1) * 8;
#pragma unroll
            for (int kt = 0; kt < 4; kt++) {
                ldsm_x4(ah[kt][0], ah[kt][1], ah[kt][2], ah[kt][3],
                        smem_u32(sxh + r*QP + kt*16 + cg));
                ldsm_x4(al[kt][0], al[kt][1], al[kt][2], al[kt][3],
                        smem_u32(sxl + r*QP + kt*16 + cg));
            }
        }

#pragma unroll
        for (int nt = 0; nt < 16; nt++) {
#pragma unroll
            for (int kt = 0; kt < 4; kt++) {
                int br = nt*8 + (lane & 7);
                int bc = kt*16 + (lane & 8);
                uint32_t b0, b1, e0, e1;
                ldsm_x2(b0, b1, smem_u32(swh + br*QP + bc));
                ldsm_x2(e0, e1, smem_u32(swl + br*QP + bc));
                mma16816(c[nt], ah[kt], b0, b1);
                mma16816(c[nt], al[kt], b0, b1);
                mma16816(c[nt], ah[kt], e0, e1);
            }
        }
        __syncthreads();
    }

    // ---- epilogue: RoPE (q,k) + qscale (q) + split-bf16 store ----
    __nv_bfloat16* oh = (mat == 0) ? g_qhi : (mat == 1) ? g_khi : g_vhi;
    __nv_bfloat16* ol = (mat == 0) ? g_qlo : (mat == 1) ? g_klo : g_vlo;
    const float qs = (mat == 0) ? 0.08838834764831845f : 1.0f;

    const int rloc = w*16 + (lane >> 2);
    const int m_lo = m0 + rloc;
    const int m_hi = m_lo + 8;
    const float pos0 = (float)(m_lo & (TT - 1));
    const float pos1 = (float)(m_hi & (TT - 1));

#pragma unroll
    for (int nt = 0; nt < 16; nt++) {
        int col = nt*8 + (lane & 3)*2;
        float e00 = c[nt][0]*qs, e01 = c[nt][1]*qs;
        float e10 = c[nt][2]*qs, e11 = c[nt][3]*qs;
        if (mat < 2) {
            int p = col >> 1;
            float freq = exp2f(-(float)p * (13.287712379549449f / 64.0f));
            float s0, c0v, s1, c1v;
            sincosf(pos0 * freq, &s0, &c0v);
            sincosf(pos1 * freq, &s1, &c1v);
            float t0 = e00*c0v - e01*s0, t1 = e00*s0 + e01*c0v;
            e00 = t0; e01 = t1;
            t0 = e10*c1v - e11*s1; t1 = e10*s1 + e11*c1v;
            e10 = t0; e11 = t1;
        }
        // split & store (row lo)
        {
            __nv_bfloat16 h0 = __float2bfloat16(e00), h1 = __float2bfloat16(e01);
            *(uint32_t*)(oh + (size_t)m_lo*HH + col) = pack_bf16x2(__bfloat162float(h0), __bfloat162float(h1));
            *(uint32_t*)(ol + (size_t)m_lo*HH + col) =
                pack_bf16x2(e00 - __bfloat162float(h0), e01 - __bfloat162float(h1));
        }
        // row hi
        {
            __nv_bfloat16 h0 = __float2bfloat16(e10), h1 = __float2bfloat16(e11);
            *(uint32_t*)(oh + (size_t)m_hi*HH + col) = pack_bf16x2(__bfloat162float(h0), __bfloat162float(h1));
            *(uint32_t*)(ol + (size_t)m_hi*HH + col) =
                pack_bf16x2(e10 - __bfloat162float(h0), e11 - __bfloat162float(h1));
        }
    }
}

// ---------------------------------------------------------------------------
// Causal flash attention via mma.sync split-bf16
// grid=(16,8), 256 threads (8 warps x 16 q-rows), q-tile 128, k-tile 64
// smem: K/V hi/lo tiles 64 rows x 128 halves, row stride AP=136 (16B-aligned pad)
// total = 4 * 64 * 136 * 2 = 69632 B (dynamic)
// ---------------------------------------------------------------------------
#define AP 136

__global__ __launch_bounds__(256) void attn_kernel(float* __restrict__ out)
{
    extern __shared__ __nv_bfloat16 sma[];
    __nv_bfloat16* kh = sma;
    __nv_bfloat16* kl = sma + 64*AP;
    __nv_bfloat16* vh = sma + 2*64*AP;
    __nv_bfloat16* vl = sma + 3*64*AP;

    const int tid = threadIdx.x;
    const int w   = tid >> 5;
    const int lane= tid & 31;
    const int b   = blockIdx.y;
    const int i0  = (gridDim.x - 1 - blockIdx.x) * 128;

    const int rloc = w*16 + (lane >> 2);
    const size_t qrow = (size_t)(b*TT + i0 + rloc) * HH;

    // Q fragments (A operand), pre-scaled hi/lo
    uint32_t qh[8][4], ql[8][4];
#pragma unroll
    for (int kt = 0; kt < 8; kt++) {
        int cb = kt*16 + (lane & 3)*2;
        qh[kt][0] = *(const uint32_t*)(g_qhi + qrow + cb);
        qh[kt][1] = *(const uint32_t*)(g_qhi + qrow + 8*HH + cb);
        qh[kt][2] = *(const uint32_t*)(g_qhi + qrow + cb + 8);
        qh[kt][3] = *(const uint32_t*)(g_qhi + qrow + 8*HH + cb + 8);
        ql[kt][0] = *(const uint32_t*)(g_qlo + qrow + cb);
        ql[kt][1] = *(const uint32_t*)(g_qlo + qrow + 8*HH + cb);
        ql[kt][2] = *(const uint32_t*)(g_qlo + qrow + cb + 8);
        ql[kt][3] = *(const uint32_t*)(g_qlo + qrow + 8*HH + cb + 8);
    }

    float o[16][4];
#pragma unroll
    for (int nt = 0; nt < 16; nt++)
#pragma unroll
        for (int e = 0; e < 4; e++) o[nt][e] = 0.0f;
    float mrow0 = -1e30f, mrow1 = -1e30f, l0 = 0.0f, l1 = 0.0f;

    const int ntiles = i0/64 + 2;
    for (int jt = 0; jt < ntiles; jt++) {
        const int j0 = jt * 64;
        __syncthreads();

        // stage K/V hi/lo tiles: 64 rows x 128 halves, stride 136, 16B segs
        {
            const size_t gbase = (size_t)(b*TT + j0) * HH;
#pragma unroll
            for (int it = 0; it < 4; it++) {
                int idx = it*256 + tid;          // 0..1023
                int row = idx >> 4, seg = idx & 15;
                *(uint4*)(kh + row*AP + seg*8) = *(const uint4*)(g_khi + gbase + (size_t)row*HH + seg*8);
            }
#pragma unroll
            for (int it = 0; it < 4; it++) {
                int idx = it*256 + tid;
                int row = idx >> 4, seg = idx & 15;
                *(uint4*)(kl + row*AP + seg*8) = *(const uint4*)(g_klo + gbase + (size_t)row*HH + seg*8);
            }
#pragma unroll
            for (int it = 0; it < 4; it++) {
                int idx = it*256 + tid;
                int row = idx >> 4, seg = idx & 15;
                *(uint4*)(vh + row*AP + seg*8) = *(const uint4*)(g_vhi + gbase + (size_t)row*HH + seg*8);
            }
#pragma unroll
            for (int it = 0; it < 4; it++) {
                int idx = it*256 + tid;
                int row = idx >> 4, seg = idx & 15;
                *(uint4*)(vl + row*AP + seg*8) = *(const uint4*)(g_vlo + gbase + (size_t)row*HH + seg*8);
            }
        }
        __syncthreads();

        // S = Q K^T (64 keys), split-bf16 3-pass
        float s[8][4];
#pragma unroll
        for (int nt = 0; nt < 8; nt++)
#pragma unroll
            for (int e = 0; e < 4; e++) s[nt][e] = 0.0f;

#pragma unroll
        for (int nt = 0; nt < 8; nt++) {
#pragma unroll
            for (int kt = 0; kt < 8; kt++) {
                int br = nt*8 + (lane & 7);
                int bc = kt*16 + (lane & 8);
                uint32_t b0, b1, e0, e1;
                ldsm_x2(b0, b1, smem_u32(kh + br*AP + bc));
                ldsm_x2(e0, e1, smem_u32(kl + br*AP + bc));
                mma16816(s[nt], qh[kt], b0, b1);
                mma16816(s[nt], ql[kt], b0, b1);
                mma16816(s[nt], qh[kt], e0, e1);
            }
        }

        // causal mask (only needed on the last two tiles)
        if (j0 >= i0) {
            int row0 = i0 + rloc;
            int row1 = row0 + 8;
#pragma unroll
            for (int nt = 0; nt < 8; nt++) {
                int colb = j0 + nt*8 + (lane & 3)*2;
                if (colb     > row0) s[nt][0] = -1e30f;
                if (colb + 1 > row0) s[nt][1] = -1e30f;
                if (colb     > row1) s[nt][2] = -1e30f;
                if (colb + 1 > row1) s[nt][3] = -1e30f;
            }
        }

        // online softmax (rows split across 4 lanes: xor 1, 2)
        float rm0 = -1e30f, rm1 = -1e30f;
#pragma unroll
        for (int nt = 0; nt < 8; nt++) {
            rm0 = fmaxf(rm0, fmaxf(s[nt][0], s[nt][1]));
            rm1 = fmaxf(rm1, fmaxf(s[nt][2], s[nt][3]));
        }
        rm0 = fmaxf(rm0, __shfl_xor_sync(0xffffffffu, rm0, 1));
        rm0 = fmaxf(rm0, __shfl_xor_sync(0xffffffffu, rm0, 2));
        rm1 = fmaxf(rm1, __shfl_xor_sync(0xffffffffu, rm1, 1));
        rm1 = fmaxf(rm1, __shfl_xor_sync(0xffffffffu, rm1, 2));

        float mn0 = fmaxf(mrow0, rm0), mn1 = fmaxf(mrow1, rm1);
        float sc0 = __expf(mrow0 - mn0), sc1 = __expf(mrow1 - mn1);
        mrow0 = mn0; mrow1 = mn1;

        float rs0 = 0.0f, rs1 = 0.0f;
        uint32_t ph[4][4], pl[4][4];
#pragma unroll
        for (int nt = 0; nt < 8; nt++) {
            float p0 = __expf(s[nt][0] - mn0);
            float p1 = __expf(s[nt][1] - mn0);
            float p2 = __expf(s[nt][2] - mn1);
            float p3 = __expf(s[nt][3] - mn1);
            rs0 += p0 + p1;
            rs1 += p2 + p3;
            float h0 = __bfloat162float(__float2bfloat16(p0));
            float h1 = __bfloat162float(__float2bfloat16(p1));
            float h2 = __bfloat162float(__float2bfloat16(p2));
            float h3 = __bfloat162float(__float2bfloat16(p3));
            int kt2 = nt >> 1;
            int hi  = (nt & 1) * 2;     // 0 -> slots 0,1 ; 1 -> slots 2,3
            ph[kt2][hi + 0] = pack_bf16x2(h0, h1);
            ph[kt2][hi + 1] = pack_bf16x2(h2, h3);
            pl[kt2][hi + 0] = pack_bf16x2(p0 - h0, p1 - h1);
            pl[kt2][hi + 1] = pack_bf16x2(p2 - h2, p3 - h3);
        }
        rs0 += __shfl_xor_sync(0xffffffffu, rs0, 1);
        rs0 += __shfl_xor_sync(0xffffffffu, rs0, 2);
        rs1 += __shfl_xor_sync(0xffffffffu, rs1, 1);
        rs1 += __shfl_xor_sync(0xffffffffu, rs1, 2);
        l0 = l0 * sc0 + rs0;
        l1 = l1 * sc1 + rs1;

        // O = O*sc + P V  (V via ldmatrix.trans, split-bf16 3-pass)
#pragma unroll
        for (int nt = 0; nt < 16; nt++) {
            o[nt][0] *= sc0; o[nt][1] *= sc0;
            o[nt][2] *= sc1; o[nt][3] *= sc1;
        }
#pragma unroll
        for (int nt = 0; nt < 16; nt++) {
#pragma unroll
            for (int kt2 = 0; kt2 < 4; kt2++) {
                int vr = kt2*16 + (lane & 7) + (lane & 8);
                int vc = nt*8;
                uint32_t b0, b1, e0, e1;
                ldsm_x2t(b0, b1, smem_u32(vh + vr*AP + vc));
                ldsm_x2t(e0, e1, smem_u32(vl + vr*AP + vc));
                mma16816(o[nt], ph[kt2], b0, b1);
                mma16816(o[nt], pl[kt2], b0, b1);
                mma16816(o[nt], ph[kt2], e0, e1);
            }
        }
    }

    // normalize + store
    float inv0 = 1.0f / l0, inv1 = 1.0f / l1;
    const size_t ob = (size_t)(b*TT + i0 + rloc) * HH;
#pragma unroll
    for (int nt = 0; nt < 16; nt++) {
        int col = nt*8 + (lane & 3)*2;
        float2 v0 = make_float2(o[nt][0]*inv0, o[nt][1]*inv0);
        float2 v1 = make_float2(o[nt][2]*inv1, o[nt][3]*inv1);
        *(float2*)(out + ob + col) = v0;
        *(float2*)(out + ob + 8*HH + col) = v1;
    }
}

// ---------------------------------------------------------------------------
extern "C" void kernel_launch(void* const* d_in, const int* in_sizes, int n_in,
                              void* d_out, int out_size)
{
    const float* x  = (const float*)d_in[0];
    const float* Wq = (const float*)d_in[1];
    const float* Wk = (const float*)d_in[2];
    const float* Wv = (const float*)d_in[3];
    float* out = (float*)d_out;

    static int attr_set = 0;
    const int qkv_smem  = 4 * 128 * QP * 2;  // 73728 B
    const int attn_smem = 4 * 64 * AP * 2;   // 69632 B
    if (!attr_set) {
        cudaFuncSetAttribute(qkv_mma_kernel,
                             cudaFuncAttributeMaxDynamicSharedMemorySize, qkv_smem);
        cudaFuncSetAttribute(attn_kernel,
                             cudaFuncAttributeMaxDynamicSharedMemorySize, attn_smem);
        attr_set = 1;
    }

    convert_x_kernel<<<MM * DD / 4 / 256, 256>>>(x);
    convert_w_kernel<<<dim3(DD * HH / 256, 3), 256>>>(Wq, Wk, Wv);
    qkv_mma_kernel<<<dim3(MM / 128, 3), 256, qkv_smem>>>();
    attn_kernel<<<dim3(TT / 128, BB), 256, attn_smem>>>(out);
}